// round 13
// baseline (speedup 1.0000x reference)
#include <cuda_runtime.h>
#include <cstdint>

#define BATCH   4096
#define SEQ     32
#define DIM     256
#define VOCAB   50257
#define NALIVE  100

// 512 ctx blocks (8 rows each) interleaved 1-per-33 among 16384 fill blocks.
#define CTXG    8
#define RATIO   33
#define NZB     16384
#define NBTOT   16896     // NZB + 512
#define TOTAL4  51463168  // BATCH*VOCAB/4

// Scratch: compacted nonzero activations per row (empty in practice).
__device__ float g_val[BATCH * NALIVE];
__device__ int   g_idx[BATCH * NALIVE];
__device__ int   g_cnt[BATCH];

__device__ __forceinline__ float warp_sum(float v) {
    #pragma unroll
    for (int off = 16; off > 0; off >>= 1)
        v += __shfl_xor_sync(0xFFFFFFFFu, v, off);
    return v;
}
__device__ __forceinline__ float warp_max(float v) {
    #pragma unroll
    for (int off = 16; off > 0; off >>= 1)
        v = fmaxf(v, __shfl_xor_sync(0xFFFFFFFFu, v, off));
    return v;
}

__global__ __launch_bounds__(256)
void fused_fill_ctx_kernel(const int*   __restrict__ tok,
                           const float* __restrict__ te,
                           const float* __restrict__ pe,
                           const float* __restrict__ q,
                           const float* __restrict__ pos,
                           float*       __restrict__ out) {
    const int bid = blockIdx.x;
    const int tid = threadIdx.x;            // 0..255

    if (bid % RATIO != 0) {
        // ---------------- zero-fill role (16384 blocks) ----------------
        const int zid = bid - (bid / RATIO + 1);         // 0..16383
        const float4 z = make_float4(0.f, 0.f, 0.f, 0.f);
        float4* __restrict__ o4 = (float4*)out;
        const long stride = (long)NZB * 256;
        for (long i = (long)zid * 256 + tid; i < (long)TOTAL4; i += stride)
            __stcs(o4 + i, z);
        return;
    }

    // -------- ctx role: 512 blocks, 8 batch rows each -----------------
    const int cid = bid / RATIO;            // 0..511

    __shared__ float s_emb[SEQ][DIM];       // 32 KB, reused per row
    __shared__ float s_ctx8[CTXG][DIM];     // 8 KB
    __shared__ float s_q[DIM];              // 1 KB
    __shared__ float s_score[SEQ];
    __shared__ float s_w[SEQ];
    __shared__ float s_act8[CTXG][NALIVE];  // 3.2 KB
    __shared__ int   s_tok[SEQ];

    const int lane = tid & 31;
    const int wid  = tid >> 5;              // 0..7

    s_q[tid] = q[tid];
    __syncthreads();

    // ---- Per-row phases A-D (te/pe read once per row) ----
    for (int r = 0; r < CTXG; r++) {
        const int b = cid * CTXG + r;
        if (tid < SEQ) s_tok[tid] = tok[b * SEQ + tid];
        __syncthreads();

        // Phase A: gather embeds into smem. 64 threads/row, 4 rows/pass.
        {
            const int rlane = tid & 63;     // float4 index within a row
            const int rgrp  = tid >> 6;     // 0..3
            #pragma unroll
            for (int p = 0; p < 8; p++) {
                const int s = p * 4 + rgrp;
                const float4 t4 = __ldg((const float4*)(te + (size_t)s_tok[s] * DIM) + rlane);
                const float4 p4 = __ldg((const float4*)(pe + s * DIM) + rlane);
                float4 e;
                e.x = t4.x + p4.x; e.y = t4.y + p4.y;
                e.z = t4.z + p4.z; e.w = t4.w + p4.w;
                *((float4*)&s_emb[s][0] + rlane) = e;
            }
        }
        __syncthreads();

        // Phase B: attention scores (warp w handles s = w, w+8, ...)
        #pragma unroll
        for (int s = wid; s < SEQ; s += 8) {
            float p = 0.f;
            #pragma unroll
            for (int i = 0; i < 8; i++) {
                int d = lane + 32 * i;
                p = fmaf(s_emb[s][d], s_q[d], p);
            }
            p = warp_sum(p);
            if (lane == 0) s_score[s] = p * (1.0f / 16.0f);   // / sqrt(256)
        }
        __syncthreads();

        // Phase C: softmax over S=32 (warp 0, one score per lane)
        if (wid == 0) {
            float sc = s_score[lane];
            float m  = warp_max(sc);
            float e  = expf(sc - m);
            float s  = warp_sum(e);
            s_w[lane] = e / s;
        }
        __syncthreads();

        // Phase D: context[d] = sum_s w[s] * embeds[s][d]
        {
            float c = 0.f;
            #pragma unroll
            for (int s = 0; s < SEQ; s++) c = fmaf(s_w[s], s_emb[s][tid], c);
            s_ctx8[r][tid] = c;
        }
        __syncthreads();
    }

    // ---- Phase E: RBF for all 8 rows; each pos row read ONCE per block ----
    for (int j = wid; j < NALIVE; j += 8) {
        float pr[8];
        #pragma unroll
        for (int i = 0; i < 8; i++) pr[i] = __ldg(pos + j * DIM + lane + 32 * i);
        #pragma unroll
        for (int r = 0; r < CTXG; r++) {
            float p = 0.f;
            #pragma unroll
            for (int i = 0; i < 8; i++) {
                const float df = s_ctx8[r][lane + 32 * i] - pr[i];
                p = fmaf(df, df, p);
            }
            p = warp_sum(p);
            if (lane == 0) s_act8[r][j] = expf(-2.0f * p);   // exp(-d2/(2*0.5^2))
        }
    }
    __syncthreads();

    // ---- Phase F: normalize + compact; warp w owns row w ----
    {
        const int r = wid;                   // 0..7
        const int b = cid * CTXG + r;
        float sum = 0.f;
        for (int j = lane; j < NALIVE; j += 32) sum += s_act8[r][j];
        sum = warp_sum(sum);
        const float denom = sum + 1e-8f;

        int cnt = 0;
        #pragma unroll
        for (int base = 0; base < 128; base += 32) {
            const int j = base + lane;
            float a = 0.f;
            bool nz = false;
            if (j < NALIVE) {
                a  = s_act8[r][j] / denom;
                nz = (a != 0.0f);
            }
            const unsigned m = __ballot_sync(0xFFFFFFFFu, nz);
            const int pre = __popc(m & ((1u << lane) - 1u));
            if (nz) {
                g_val[b * NALIVE + cnt + pre] = a;
                g_idx[b * NALIVE + cnt + pre] = j;
            }
            cnt += __popc(m);
        }
        if (lane == 0) g_cnt[b] = cnt;
    }
}

// Sparse fixup: 16 blocks, each checks 256 rows IN PARALLEL (one load round),
// exits immediately when all counts are zero (the common case, ~4 us).
__global__ __launch_bounds__(256)
void fixup_kernel(const float* __restrict__ W, float* __restrict__ out) {
    __shared__ int   s_cnt_arr[256];
    __shared__ float s_val[NALIVE];
    __shared__ int   s_idx[NALIVE];

    const int tid = threadIdx.x;
    const int b0  = blockIdx.x * 256;

    const int mycnt = g_cnt[b0 + tid];
    s_cnt_arr[tid] = mycnt;
    if (__syncthreads_count(mycnt != 0) == 0) return;   // all-zero: exit

    for (int r = 0; r < 256; r++) {
        const int cnt = s_cnt_arr[r];
        if (cnt == 0) continue;
        const int b = b0 + r;

        if (tid < cnt) {
            s_val[tid] = g_val[b * NALIVE + tid];
            s_idx[tid] = g_idx[b * NALIVE + tid];
        }
        __syncthreads();

        float* __restrict__ orow = out + (size_t)b * VOCAB;
        for (int v = tid; v < VOCAB; v += 256) {
            float acc = 0.f;
            for (int k = 0; k < cnt; k++)
                acc = fmaf(s_val[k], W[(size_t)s_idx[k] * VOCAB + v], acc);
            orow[v] = acc;
        }
        __syncthreads();
    }
}

extern "C" void kernel_launch(void* const* d_in, const int* in_sizes, int n_in,
                              void* d_out, int out_size) {
    const int*   tok = (const int*)  d_in[0];   // [B, S]
    const float* te  = (const float*)d_in[1];   // [V, D]
    const float* pe  = (const float*)d_in[2];   // [S, D]
    const float* q   = (const float*)d_in[3];   // [D]
    const float* pos = (const float*)d_in[4];   // [N, D]
    const float* W   = (const float*)d_in[5];   // [N, V]
    float* out = (float*)d_out;                 // [B, V]

    fused_fill_ctx_kernel<<<NBTOT, 256>>>(tok, te, pe, q, pos, out);
    fixup_kernel<<<16, 256>>>(W, out);
}